// round 16
// baseline (speedup 1.0000x reference)
#include <cuda_runtime.h>
#include <math.h>

// Problem constants (fixed shapes)
#define B      2
#define HEADS  8
#define CQ     48
#define CK     12
#define CTOT   384      // HEADS*CQ
#define P      96       // pooled channels = HEADS*CK
#define L      4096
#define TREP   16
#define HW     65536    // 256*256 = TREP*L
#define NROWS  (B*CTOT)     // 768 q rows
#define KROWS  (B*P)        // 192 k rows

typedef unsigned long long ull;

// Scratch (static device globals — no allocation)
__device__ float g_kn[KROWS * L];      // pooled + L2-normalized kv   (3.1 MB)
__device__ float g_attn[NROWS * CK];   // softmax(attn)

__device__ __forceinline__ float warpSum(float v) {
#pragma unroll
    for (int o = 16; o > 0; o >>= 1) v += __shfl_xor_sync(0xffffffffu, v, o);
    return v;
}

#if defined(__CUDA_ARCH__) && (__CUDA_ARCH__ >= 1000)
__device__ __forceinline__ ull pack2(float x) {      // (x, x) as f32x2
    ull r;
    asm("mov.b64 %0, {%1, %1};" : "=l"(r) : "f"(x));
    return r;
}
__device__ __forceinline__ void ffma2(ull& d, ull a, ull b) {  // d += a*b (2x fp32)
    asm("fma.rn.f32x2 %0, %1, %2, %0;" : "+l"(d) : "l"(a), "l"(b));
}
#else
__device__ __forceinline__ ull pack2(float x) {
    union { float f[2]; ull u; } t; t.f[0] = x; t.f[1] = x; return t.u;
}
__device__ __forceinline__ void ffma2(ull& d, ull a, ull b) {
    union { float f[2]; ull u; } da, aa, ba;
    da.u = d; aa.u = a; ba.u = b;
    da.f[0] = fmaf(aa.f[0], ba.f[0], da.f[0]);
    da.f[1] = fmaf(aa.f[1], ba.f[1], da.f[1]);
    d = da.u;
}
#endif

// ---------------------------------------------------------------------------
// K2: avg_pool1d + L2 normalize (192 blocks, both batches).
// ---------------------------------------------------------------------------
__global__ void __launch_bounds__(1024) k_pool_kv(const float* __restrict__ kv) {
    int row = blockIdx.x;               // b*P + i
    int b = row / P, i = row % P;
    int tid = threadIdx.x;
    const float4* base = reinterpret_cast<const float4*>(kv + ((size_t)b * CTOT + 4 * i) * L);
    float4 v0 = base[tid];
    float4 v1 = base[1024 + tid];
    float4 v2 = base[2048 + tid];
    float4 v3 = base[3072 + tid];
    float4 p;
    p.x = 0.25f * (v0.x + v1.x + v2.x + v3.x);
    p.y = 0.25f * (v0.y + v1.y + v2.y + v3.y);
    p.z = 0.25f * (v0.z + v1.z + v2.z + v3.z);
    p.w = 0.25f * (v0.w + v1.w + v2.w + v3.w);
    float ss = p.x * p.x + p.y * p.y + p.z * p.z + p.w * p.w;

    ss = warpSum(ss);
    __shared__ float sred[32];
    __shared__ float s_scale;
    int lane = tid & 31, w = tid >> 5;
    if (lane == 0) sred[w] = ss;
    __syncthreads();
    if (w == 0) {
        float v = sred[lane];
        v = warpSum(v);
        if (lane == 0) s_scale = 1.f / fmaxf(sqrtf(v), 1e-12f);
    }
    __syncthreads();
    float sc = s_scale;
    p.x *= sc; p.y *= sc; p.z *= sc; p.w *= sc;
    reinterpret_cast<float4*>(g_kn + (size_t)row * L)[tid] = p;
}

// ---------------------------------------------------------------------------
// K1: fold Q + dot vs 12 kn rows + softmax. 384 blocks x 256 thr; 2 rows
// sequentially per block. MLP=8: two t-tiles of loads batched per iteration
// (8 outstanding LDG.128/thread) to deepen the DRAM read queue past the
// 4.4TB/s plateau measured at MLP=4.
// ---------------------------------------------------------------------------
__global__ void __launch_bounds__(256) k_fold_attn(const float* __restrict__ Q) {
    int row0 = blockIdx.x * 2;
    int b = row0 / CTOT;
    int c = row0 % CTOT;
    int h = c / CQ;                     // both rows share (b,h): 2 | CQ
    int tid = threadIdx.x;
    int lane = tid & 31, w = tid >> 5;

    const float4* kb = reinterpret_cast<const float4*>(g_kn + ((size_t)b * P + h * CK) * L);

    __shared__ float sp[8][CK + 1];
    __shared__ float fin[CK + 1];

#pragma unroll
    for (int r = 0; r < 2; r++) {
        int row = row0 + r;
        if (r) __syncthreads();         // protect sp/fin reuse

        const float4* qp = reinterpret_cast<const float4*>(Q + (size_t)row * HW);
        float4 acc[4];
#pragma unroll
        for (int cc = 0; cc < 4; cc++) acc[cc] = make_float4(0.f, 0.f, 0.f, 0.f);
        float ss = 0.f;

#pragma unroll
        for (int t = 0; t < TREP; t += 2) {
            float4 v[8];                // 8 outstanding loads (2 t-tiles)
#pragma unroll
            for (int cc = 0; cc < 4; cc++) v[cc]     = qp[t * 1024 + cc * 256 + tid];
#pragma unroll
            for (int cc = 0; cc < 4; cc++) v[4 + cc] = qp[(t + 1) * 1024 + cc * 256 + tid];
#pragma unroll
            for (int u = 0; u < 8; u++) {
                int cc = u & 3;
                acc[cc].x += v[u].x; acc[cc].y += v[u].y;
                acc[cc].z += v[u].z; acc[cc].w += v[u].w;
                ss += v[u].x * v[u].x + v[u].y * v[u].y +
                      v[u].z * v[u].z + v[u].w * v[u].w;
            }
        }

        float dk[CK];
#pragma unroll
        for (int kk = 0; kk < CK; kk++) {
            float s = 0.f;
#pragma unroll
            for (int cc = 0; cc < 4; cc++) {
                float4 kv4 = kb[kk * 1024 + cc * 256 + tid];
                s += acc[cc].x * kv4.x + acc[cc].y * kv4.y +
                     acc[cc].z * kv4.z + acc[cc].w * kv4.w;
            }
            dk[kk] = s;
        }

        ss = warpSum(ss);
#pragma unroll
        for (int kk = 0; kk < CK; kk++) dk[kk] = warpSum(dk[kk]);

        if (lane == 0) {
#pragma unroll
            for (int kk = 0; kk < CK; kk++) sp[w][kk] = dk[kk];
            sp[w][CK] = ss;
        }
        __syncthreads();
        if (tid < CK + 1) {
            float s = 0.f;
#pragma unroll
            for (int ww = 0; ww < 8; ww++) s += sp[ww][tid];
            fin[tid] = s;
        }
        __syncthreads();
        if (tid < CK) {
            float inv = 1.f / fmaxf(sqrtf(fin[CK]), 1e-12f);
            float mx = -1e30f;
#pragma unroll
            for (int k2 = 0; k2 < CK; k2++) mx = fmaxf(mx, fin[k2] * inv);
            float sum = 0.f;
#pragma unroll
            for (int k2 = 0; k2 < CK; k2++) sum += expf(fin[k2] * inv - mx);
            g_attn[(size_t)row * CK + tid] = expf(fin[tid] * inv - mx) / sum;
        }
    }
}

// ---------------------------------------------------------------------------
// K5 (fully fused, j-split pipeline — R15-measured best, unchanged):
// M prologue + f = M @ kn + replicated stores. Two 512-j halves; each kn
// column read exactly once; half-0 stores drain under half-1 compute.
// Block tile: 8 o-rows x 1024 j. Grid (jt=4, ot=48, b=2) = 384 blocks x 128.
// ---------------------------------------------------------------------------
__global__ void __launch_bounds__(128) k_out_fused(float* __restrict__ out,
                                                   const float* __restrict__ W) {
    __shared__ float sW[8 * CTOT];      // 12 KB
    __shared__ float sA[CTOT * CK];     // 18 KB
    __shared__ ull sMp[8 * P];          // packed (m,m) pairs, 6 KB
    int jt = blockIdx.x, ot = blockIdx.y, b = blockIdx.z;
    int tid = threadIdx.x;

    // --- Prologue: stage W + attn, compute packed M ---
    const float4* wp = reinterpret_cast<const float4*>(W + (size_t)(ot * 8) * CTOT);
    for (int i = tid; i < 8 * CTOT / 4; i += 128)
        reinterpret_cast<float4*>(sW)[i] = wp[i];
    const float4* ap = reinterpret_cast<const float4*>(g_attn + (size_t)b * CTOT * CK);
    for (int i = tid; i < CTOT * CK / 4; i += 128)
        reinterpret_cast<float4*>(sA)[i] = ap[i];
    __syncthreads();

#pragma unroll
    for (int e = 0; e < 6; e++) {
        int idx = e * 128 + tid;        // 768 entries = 8 rows x 96 p
        int oi = idx / P;
        int p  = idx % P;
        int h = p / CK, kk = p % CK;
        const float* wrow = sW + oi * CTOT + h * CQ;
        const float* acol = sA + (h * CQ) * CK + kk;
        float s = 0.f;
#pragma unroll
        for (int cc = 0; cc < CQ; cc++) s += wrow[cc] * acol[cc * CK];
        sMp[oi * P + p] = pack2(s);
    }
    __syncthreads();

    // --- Mainloop: two j-halves; all 8 o-rows accumulated per half ---
#pragma unroll
    for (int half = 0; half < 2; half++) {
        int j = jt * 1024 + half * 512 + tid * 4;
        const float* knb = g_kn + (size_t)b * P * L + j;

        ull accLo[8], accHi[8];
#pragma unroll
        for (int oi = 0; oi < 8; oi++) { accLo[oi] = 0ULL; accHi[oi] = 0ULL; }

#pragma unroll 3
        for (int pg = 0; pg < 24; pg++) {
            ulonglong2 kq[4];
#pragma unroll
            for (int r = 0; r < 4; r++)
                kq[r] = *reinterpret_cast<const ulonglong2*>(knb + (size_t)(pg * 4 + r) * L);
#pragma unroll
            for (int oi = 0; oi < 8; oi++) {
                const ull* mrow = &sMp[oi * P + pg * 4];
                ulonglong2 mp0 = *reinterpret_cast<const ulonglong2*>(mrow);
                ulonglong2 mp1 = *reinterpret_cast<const ulonglong2*>(mrow + 2);
                ffma2(accLo[oi], kq[0].x, mp0.x); ffma2(accHi[oi], kq[0].y, mp0.x);
                ffma2(accLo[oi], kq[1].x, mp0.y); ffma2(accHi[oi], kq[1].y, mp0.y);
                ffma2(accLo[oi], kq[2].x, mp1.x); ffma2(accHi[oi], kq[2].y, mp1.x);
                ffma2(accLo[oi], kq[3].x, mp1.y); ffma2(accHi[oi], kq[3].y, mp1.y);
            }
        }

        // Stores for this j-half (drain overlaps next half's compute).
#pragma unroll
        for (int oi = 0; oi < 8; oi++) {
            union { ull u[2]; float4 f; } cvt;
            cvt.u[0] = accLo[oi];
            cvt.u[1] = accHi[oi];
            float4 v = cvt.f;
            size_t base = ((size_t)(b * CTOT + ot * 8 + oi)) * HW + j;
            float4* op = reinterpret_cast<float4*>(out + base);
#pragma unroll
            for (int t = 0; t < TREP; t++)
                __stcs(op + t * 1024, v);
        }
    }
}

// ---------------------------------------------------------------------------
extern "C" void kernel_launch(void* const* d_in, const int* in_sizes, int n_in,
                              void* d_out, int out_size) {
    const float* Q  = (const float*)d_in[0];
    const float* kv = (const float*)d_in[1];
    const float* W  = (const float*)d_in[2];
    float* out = (float*)d_out;

    k_pool_kv<<<KROWS, 1024>>>(kv);
    k_fold_attn<<<NROWS / 2, 256>>>(Q);
    dim3 go(4, 48, 2);
    k_out_fused<<<go, 128>>>(out, W);
}

// round 17
// speedup vs baseline: 1.0179x; 1.0179x over previous
#include <cuda_runtime.h>
#include <math.h>

// Problem constants (fixed shapes)
#define B      2
#define HEADS  8
#define CQ     48
#define CK     12
#define CTOT   384      // HEADS*CQ
#define P      96       // pooled channels = HEADS*CK
#define L      4096
#define TREP   16
#define HW     65536    // 256*256 = TREP*L
#define NROWS  (B*CTOT)     // 768 q rows
#define KROWS  (B*P)        // 192 k rows

typedef unsigned long long ull;

// Scratch (static device globals — no allocation)
__device__ float g_kn[KROWS * L];      // pooled + L2-normalized kv   (3.1 MB)
__device__ float g_attn[NROWS * CK];   // softmax(attn)
__device__ int   g_ready = 0;          // pool-done counter (reset by out_fused)

__device__ __forceinline__ float warpSum(float v) {
#pragma unroll
    for (int o = 16; o > 0; o >>= 1) v += __shfl_xor_sync(0xffffffffu, v, o);
    return v;
}

#if defined(__CUDA_ARCH__) && (__CUDA_ARCH__ >= 1000)
__device__ __forceinline__ ull pack2(float x) {      // (x, x) as f32x2
    ull r;
    asm("mov.b64 %0, {%1, %1};" : "=l"(r) : "f"(x));
    return r;
}
__device__ __forceinline__ void ffma2(ull& d, ull a, ull b) {  // d += a*b (2x fp32)
    asm("fma.rn.f32x2 %0, %1, %2, %0;" : "+l"(d) : "l"(a), "l"(b));
}
#else
__device__ __forceinline__ ull pack2(float x) {
    union { float f[2]; ull u; } t; t.f[0] = x; t.f[1] = x; return t.u;
}
__device__ __forceinline__ void ffma2(ull& d, ull a, ull b) {
    union { float f[2]; ull u; } da, aa, ba;
    da.u = d; aa.u = a; ba.u = b;
    da.f[0] = fmaf(aa.f[0], ba.f[0], da.f[0]);
    da.f[1] = fmaf(aa.f[1], ba.f[1], da.f[1]);
    d = da.u;
}
#endif

// ---------------------------------------------------------------------------
// K1+K2 fused: blocks 0..191 pool+normalize kv -> g_kn, signal g_ready.
// Blocks 192..575 fold Q (no kn needed, ~45us), then wait for g_ready
// (satisfied ~38us earlier by dispatch order) and run the kn-dot + softmax.
// 576 blocks x 256 thr; all resident at ~60 regs (<= ~592 slots): pool blocks
// (lowest IDs) start first and finish in ~7us -> the spin never waits.
// ---------------------------------------------------------------------------
__global__ void __launch_bounds__(256) k_pool_attn(const float* __restrict__ Q,
                                                   const float* __restrict__ kv) {
    int tid = threadIdx.x;
    int lane = tid & 31, w = tid >> 5;

    if (blockIdx.x < KROWS) {
        // ---------------- pool branch (row = blockIdx.x) ----------------
        int row = blockIdx.x;
        int b = row / P, i = row % P;
        const float4* base = reinterpret_cast<const float4*>(kv + ((size_t)b * CTOT + 4 * i) * L);

        float4 p[4];
        float ss = 0.f;
#pragma unroll
        for (int c = 0; c < 4; c++) {
            float4 s = make_float4(0.f, 0.f, 0.f, 0.f);
#pragma unroll
            for (int src = 0; src < 4; src++) {
                float4 v = base[src * 1024 + c * 256 + tid];
                s.x += v.x; s.y += v.y; s.z += v.z; s.w += v.w;
            }
            p[c].x = 0.25f * s.x; p[c].y = 0.25f * s.y;
            p[c].z = 0.25f * s.z; p[c].w = 0.25f * s.w;
            ss += p[c].x * p[c].x + p[c].y * p[c].y +
                  p[c].z * p[c].z + p[c].w * p[c].w;
        }

        ss = warpSum(ss);
        __shared__ float sred[8];
        __shared__ float s_scale;
        if (lane == 0) sred[w] = ss;
        __syncthreads();
        if (tid == 0) {
            float v = 0.f;
#pragma unroll
            for (int ww = 0; ww < 8; ww++) v += sred[ww];
            s_scale = 1.f / fmaxf(sqrtf(v), 1e-12f);
        }
        __syncthreads();
        float sc = s_scale;
        float4* kout = reinterpret_cast<float4*>(g_kn + (size_t)row * L);
#pragma unroll
        for (int c = 0; c < 4; c++) {
            float4 o;
            o.x = p[c].x * sc; o.y = p[c].y * sc;
            o.z = p[c].z * sc; o.w = p[c].w * sc;
            kout[c * 256 + tid] = o;
        }
        __threadfence();                 // release kn writes
        __syncthreads();
        if (tid == 0) atomicAdd(&g_ready, 1);
        return;
    }

    // ---------------- fold_attn branch (2 rows per block) ----------------
    int row0 = (blockIdx.x - KROWS) * 2;
    int b = row0 / CTOT;
    int c = row0 % CTOT;
    int h = c / CQ;                     // both rows share (b,h): 2 | CQ

    const float4* kb = reinterpret_cast<const float4*>(g_kn + ((size_t)b * P + h * CK) * L);

    __shared__ float sp[8][CK + 1];
    __shared__ float fin[CK + 1];

#pragma unroll
    for (int r = 0; r < 2; r++) {
        int row = row0 + r;
        if (r) __syncthreads();         // protect sp/fin reuse

        const float4* qp = reinterpret_cast<const float4*>(Q + (size_t)row * HW);
        float4 acc[4];
#pragma unroll
        for (int cc = 0; cc < 4; cc++) acc[cc] = make_float4(0.f, 0.f, 0.f, 0.f);
        float ss = 0.f;

#pragma unroll
        for (int t = 0; t < TREP; t++) {
            float4 v[4];
#pragma unroll
            for (int cc = 0; cc < 4; cc++) v[cc] = qp[t * 1024 + cc * 256 + tid];
#pragma unroll
            for (int cc = 0; cc < 4; cc++) {
                acc[cc].x += v[cc].x; acc[cc].y += v[cc].y;
                acc[cc].z += v[cc].z; acc[cc].w += v[cc].w;
                ss += v[cc].x * v[cc].x + v[cc].y * v[cc].y +
                      v[cc].z * v[cc].z + v[cc].w * v[cc].w;
            }
        }

        // Wait for pooling to be complete (satisfied long before we get here).
        if (r == 0) {
            if (tid == 0) {
                while (*((volatile int*)&g_ready) < KROWS) __nanosleep(64);
            }
            __syncthreads();
            __threadfence();            // acquire: order kn loads after flag
        }

        float dk[CK];
#pragma unroll
        for (int kk = 0; kk < CK; kk++) {
            float s = 0.f;
#pragma unroll
            for (int cc = 0; cc < 4; cc++) {
                float4 kv4 = kb[kk * 1024 + cc * 256 + tid];
                s += acc[cc].x * kv4.x + acc[cc].y * kv4.y +
                     acc[cc].z * kv4.z + acc[cc].w * kv4.w;
            }
            dk[kk] = s;
        }

        ss = warpSum(ss);
#pragma unroll
        for (int kk = 0; kk < CK; kk++) dk[kk] = warpSum(dk[kk]);

        if (lane == 0) {
#pragma unroll
            for (int kk = 0; kk < CK; kk++) sp[w][kk] = dk[kk];
            sp[w][CK] = ss;
        }
        __syncthreads();
        if (tid < CK + 1) {
            float s = 0.f;
#pragma unroll
            for (int ww = 0; ww < 8; ww++) s += sp[ww][tid];
            fin[tid] = s;
        }
        __syncthreads();
        if (tid < CK) {
            float inv = 1.f / fmaxf(sqrtf(fin[CK]), 1e-12f);
            float mx = -1e30f;
#pragma unroll
            for (int k2 = 0; k2 < CK; k2++) mx = fmaxf(mx, fin[k2] * inv);
            float sum = 0.f;
#pragma unroll
            for (int k2 = 0; k2 < CK; k2++) sum += expf(fin[k2] * inv - mx);
            g_attn[(size_t)row * CK + tid] = expf(fin[tid] * inv - mx) / sum;
        }
    }
}

// ---------------------------------------------------------------------------
// K5 (fully fused, j-split pipeline — R15-measured best, unchanged except
// the g_ready reset for the next graph replay):
// Block tile: 8 o-rows x 1024 j. Grid (jt=4, ot=48, b=2) = 384 blocks x 128.
// ---------------------------------------------------------------------------
__global__ void __launch_bounds__(128) k_out_fused(float* __restrict__ out,
                                                   const float* __restrict__ W) {
    __shared__ float sW[8 * CTOT];      // 12 KB
    __shared__ float sA[CTOT * CK];     // 18 KB
    __shared__ ull sMp[8 * P];          // packed (m,m) pairs, 6 KB
    int jt = blockIdx.x, ot = blockIdx.y, b = blockIdx.z;
    int tid = threadIdx.x;

    // Reset the pool-done counter for the next replay (this kernel is ordered
    // after k_pool_attn in-stream, so no race with the spin).
    if (jt == 0 && ot == 0 && b == 0 && tid == 0) g_ready = 0;

    // --- Prologue: stage W + attn, compute packed M ---
    const float4* wp = reinterpret_cast<const float4*>(W + (size_t)(ot * 8) * CTOT);
    for (int i = tid; i < 8 * CTOT / 4; i += 128)
        reinterpret_cast<float4*>(sW)[i] = wp[i];
    const float4* ap = reinterpret_cast<const float4*>(g_attn + (size_t)b * CTOT * CK);
    for (int i = tid; i < CTOT * CK / 4; i += 128)
        reinterpret_cast<float4*>(sA)[i] = ap[i];
    __syncthreads();

#pragma unroll
    for (int e = 0; e < 6; e++) {
        int idx = e * 128 + tid;        // 768 entries = 8 rows x 96 p
        int oi = idx / P;
        int p  = idx % P;
        int h = p / CK, kk = p % CK;
        const float* wrow = sW + oi * CTOT + h * CQ;
        const float* acol = sA + (h * CQ) * CK + kk;
        float s = 0.f;
#pragma unroll
        for (int cc = 0; cc < CQ; cc++) s += wrow[cc] * acol[cc * CK];
        sMp[oi * P + p] = pack2(s);
    }
    __syncthreads();

    // --- Mainloop: two j-halves; all 8 o-rows accumulated per half ---
#pragma unroll
    for (int half = 0; half < 2; half++) {
        int j = jt * 1024 + half * 512 + tid * 4;
        const float* knb = g_kn + (size_t)b * P * L + j;

        ull accLo[8], accHi[8];
#pragma unroll
        for (int oi = 0; oi < 8; oi++) { accLo[oi] = 0ULL; accHi[oi] = 0ULL; }

#pragma unroll 3
        for (int pg = 0; pg < 24; pg++) {
            ulonglong2 kq[4];
#pragma unroll
            for (int r = 0; r < 4; r++)
                kq[r] = *reinterpret_cast<const ulonglong2*>(knb + (size_t)(pg * 4 + r) * L);
#pragma unroll
            for (int oi = 0; oi < 8; oi++) {
                const ull* mrow = &sMp[oi * P + pg * 4];
                ulonglong2 mp0 = *reinterpret_cast<const ulonglong2*>(mrow);
                ulonglong2 mp1 = *reinterpret_cast<const ulonglong2*>(mrow + 2);
                ffma2(accLo[oi], kq[0].x, mp0.x); ffma2(accHi[oi], kq[0].y, mp0.x);
                ffma2(accLo[oi], kq[1].x, mp0.y); ffma2(accHi[oi], kq[1].y, mp0.y);
                ffma2(accLo[oi], kq[2].x, mp1.x); ffma2(accHi[oi], kq[2].y, mp1.x);
                ffma2(accLo[oi], kq[3].x, mp1.y); ffma2(accHi[oi], kq[3].y, mp1.y);
            }
        }

        // Stores for this j-half (drain overlaps next half's compute).
#pragma unroll
        for (int oi = 0; oi < 8; oi++) {
            union { ull u[2]; float4 f; } cvt;
            cvt.u[0] = accLo[oi];
            cvt.u[1] = accHi[oi];
            float4 v = cvt.f;
            size_t base = ((size_t)(b * CTOT + ot * 8 + oi)) * HW + j;
            float4* op = reinterpret_cast<float4*>(out + base);
#pragma unroll
            for (int t = 0; t < TREP; t++)
                __stcs(op + t * 1024, v);
        }
    }
}

// ---------------------------------------------------------------------------
extern "C" void kernel_launch(void* const* d_in, const int* in_sizes, int n_in,
                              void* d_out, int out_size) {
    const float* Q  = (const float*)d_in[0];
    const float* kv = (const float*)d_in[1];
    const float* W  = (const float*)d_in[2];
    float* out = (float*)d_out;

    k_pool_attn<<<KROWS + NROWS / 2, 256>>>(Q, kv);
    dim3 go(4, 48, 2);
    k_out_fused<<<go, 128>>>(out, W);
}